// round 3
// baseline (speedup 1.0000x reference)
#include <cuda_runtime.h>

#define B_  16384
#define H_  1024
#define BH_ (B_ * H_)

// Scratch: k, v, r logits (r is overwritten with sigmoid(r)*wkv by the wkv kernel)
__device__ float g_k[BH_];
__device__ float g_v[BH_];
__device__ float g_r[BH_];

// Packed fp32x2 FMA (Blackwell FFMA2 — only reachable via PTX)
#define PACK2(dst, v32) asm("mov.b64 %0, {%1, %1};" : "=l"(dst) : "r"(v32))
#define FMA2(c, a, b)   asm("fma.rn.f32x2 %0, %1, %2, %0;" : "+l"(c) : "l"(a), "l"(b))

// C[M,N] = A[M,K] @ W[N,K]^T      (A optionally mixed on the fly: a = alpha + (x - alpha)*tm)
template <bool MIX>
__device__ __forceinline__ void gemm_body(
    const float* __restrict__ A, const float* __restrict__ Aalt,
    const float* __restrict__ tmix, const float* __restrict__ W,
    float* __restrict__ C)
{
    constexpr int BM = 128, BN = 128, BK = 16, TM = 8, TN = 8;
    constexpr int K = H_, N = H_;
    constexpr int PAD = 4;  // keeps 16B alignment of [kk] rows; breaks STS conflicts

    __shared__ __align__(16) float As[BK][BM + PAD];
    __shared__ __align__(16) float Bs[BK][BN + PAD];

    const int tid  = threadIdx.x;
    const int tx   = tid & 15;
    const int ty   = tid >> 4;
    const int m0   = blockIdx.y * BM;
    const int n0   = blockIdx.x * BN;
    const int rowb = ty * TM;
    const int colb = tx * TN;

    unsigned long long c2[TM][TN / 2];
#pragma unroll
    for (int i = 0; i < TM; i++)
#pragma unroll
        for (int j = 0; j < TN / 2; j++) c2[i][j] = 0ULL;

    const int r0 = tid >> 2;          // 0..63
    const int c4 = (tid & 3) << 2;    // 0,4,8,12

    for (int kt = 0; kt < K; kt += BK) {
        // ---- load A (mixed) and B tiles, transposed into [k][m]/[k][n] ----
#pragma unroll
        for (int it = 0; it < 2; ++it) {
            const int r = r0 + it * 64;

            const float4 xv = *reinterpret_cast<const float4*>(&A[(m0 + r) * K + kt + c4]);
            float4 val4;
            if (MIX) {
                const float4 av  = *reinterpret_cast<const float4*>(&Aalt[(m0 + r) * K + kt + c4]);
                const float4 tm4 = *reinterpret_cast<const float4*>(&tmix[kt + c4]);
                val4.x = fmaf(xv.x - av.x, tm4.x, av.x);
                val4.y = fmaf(xv.y - av.y, tm4.y, av.y);
                val4.z = fmaf(xv.z - av.z, tm4.z, av.z);
                val4.w = fmaf(xv.w - av.w, tm4.w, av.w);
            } else {
                val4 = xv;
            }
            As[c4 + 0][r] = val4.x;
            As[c4 + 1][r] = val4.y;
            As[c4 + 2][r] = val4.z;
            As[c4 + 3][r] = val4.w;

            const float4 wv = *reinterpret_cast<const float4*>(&W[(n0 + r) * K + kt + c4]);
            Bs[c4 + 0][r] = wv.x;
            Bs[c4 + 1][r] = wv.y;
            Bs[c4 + 2][r] = wv.z;
            Bs[c4 + 3][r] = wv.w;
        }
        __syncthreads();

        // ---- compute: 8x8 per thread, FFMA2 on column pairs ----
#pragma unroll
        for (int kk = 0; kk < BK; ++kk) {
            const float4 a0 = *reinterpret_cast<const float4*>(&As[kk][rowb]);
            const float4 a1 = *reinterpret_cast<const float4*>(&As[kk][rowb + 4]);
            const ulonglong2 q0 = *reinterpret_cast<const ulonglong2*>(&Bs[kk][colb]);
            const ulonglong2 q1 = *reinterpret_cast<const ulonglong2*>(&Bs[kk][colb + 4]);
            const unsigned long long b2[4] = {q0.x, q0.y, q1.x, q1.y};
            const float av[8] = {a0.x, a0.y, a0.z, a0.w, a1.x, a1.y, a1.z, a1.w};
#pragma unroll
            for (int i = 0; i < TM; i++) {
                unsigned long long a2;
                PACK2(a2, __float_as_uint(av[i]));
#pragma unroll
                for (int j = 0; j < TN / 2; j++) FMA2(c2[i][j], a2, b2[j]);
            }
        }
        __syncthreads();
    }

    // ---- epilogue ----
#pragma unroll
    for (int i = 0; i < TM; i++) {
        float4 o0, o1;
        reinterpret_cast<unsigned long long*>(&o0)[0] = c2[i][0];
        reinterpret_cast<unsigned long long*>(&o0)[1] = c2[i][1];
        reinterpret_cast<unsigned long long*>(&o1)[0] = c2[i][2];
        reinterpret_cast<unsigned long long*>(&o1)[1] = c2[i][3];
        float* dst = &C[(m0 + rowb + i) * N + n0 + colb];
        *reinterpret_cast<float4*>(dst)     = o0;
        *reinterpret_cast<float4*>(dst + 4) = o1;
    }
}

// Phase 1: k/v/r logits, one launch, grid.z selects the GEMM.
__global__ __launch_bounds__(256, 2)
void gemm3_kernel(const float* __restrict__ x, const float* __restrict__ alpha,
                  const float* __restrict__ tmk, const float* __restrict__ tmv,
                  const float* __restrict__ tmr,
                  const float* __restrict__ Wk, const float* __restrict__ Wv,
                  const float* __restrict__ Wr)
{
    const int z = blockIdx.z;
    const float* tm = (z == 0) ? tmk : (z == 1) ? tmv : tmr;
    const float* W  = (z == 0) ? Wk  : (z == 1) ? Wv  : Wr;
    float*       C  = (z == 0) ? g_k : (z == 1) ? g_v : g_r;
    gemm_body<true>(x, alpha, tm, W, C);
}

// Phase 3: out = rwkv @ Wo^T  into d_out section 0.
__global__ __launch_bounds__(256, 2)
void gemm_o_kernel(const float* __restrict__ Wo, float* __restrict__ out)
{
    gemm_body<false>(g_r, nullptr, nullptr, Wo, out);
}

// Phase 2: pointwise WKV + state update. Writes output sections 1..4 and
// overwrites g_r with sigmoid(r)*wkv (input to phase 3).
__global__ __launch_bounds__(256)
void wkv_kernel(const float* __restrict__ x,  const float* __restrict__ aa,
                const float* __restrict__ bb, const float* __restrict__ pp,
                const float* __restrict__ td, const float* __restrict__ tf,
                float* __restrict__ out)
{
    const int idx  = blockIdx.x * blockDim.x + threadIdx.x;
    const int base = idx << 2;
    const int h    = base & (H_ - 1);

    const float4 k4  = *reinterpret_cast<const float4*>(&g_k[base]);
    const float4 v4  = *reinterpret_cast<const float4*>(&g_v[base]);
    const float4 r4  = *reinterpret_cast<const float4*>(&g_r[base]);
    const float4 a4  = *reinterpret_cast<const float4*>(&aa[base]);
    const float4 b4  = *reinterpret_cast<const float4*>(&bb[base]);
    const float4 p4  = *reinterpret_cast<const float4*>(&pp[base]);
    const float4 x4  = *reinterpret_cast<const float4*>(&x[base]);
    const float4 tf4 = *reinterpret_cast<const float4*>(&tf[h]);
    const float4 td4 = *reinterpret_cast<const float4*>(&td[h]);

    float4 o_rw, o_naa, o_nbb, o_q2;
    const float* kf  = reinterpret_cast<const float*>(&k4);
    const float* vf  = reinterpret_cast<const float*>(&v4);
    const float* rf  = reinterpret_cast<const float*>(&r4);
    const float* af  = reinterpret_cast<const float*>(&a4);
    const float* bf  = reinterpret_cast<const float*>(&b4);
    const float* pf  = reinterpret_cast<const float*>(&p4);
    const float* tff = reinterpret_cast<const float*>(&tf4);
    const float* tdf = reinterpret_cast<const float*>(&td4);
    float* rw  = reinterpret_cast<float*>(&o_rw);
    float* naa = reinterpret_cast<float*>(&o_naa);
    float* nbb = reinterpret_cast<float*>(&o_nbb);
    float* oq2 = reinterpret_cast<float*>(&o_q2);

#pragma unroll
    for (int j = 0; j < 4; j++) {
        const float k = kf[j], v = vf[j], a = af[j], b = bf[j], p = pf[j];
        const float r = 1.0f / (1.0f + expf(-rf[j]));

        const float ww  = tff[j] + k;
        const float qq  = fmaxf(p, ww);
        const float e1  = expf(p - qq);
        const float e2  = expf(ww - qq);
        const float wkv = (e1 * a + e2 * v) / (e1 * b + e2);
        rw[j] = r * wkv;

        const float ww2 = p + tdf[j];
        const float q2  = fmaxf(ww2, k);
        const float e1b = expf(ww2 - q2);
        const float e2b = expf(k - q2);
        naa[j] = e1b * a + e2b * v;
        nbb[j] = e1b * b + e2b;
        oq2[j] = q2;
    }

    *reinterpret_cast<float4*>(&g_r[base])            = o_rw;   // rwkv -> phase-3 input
    *reinterpret_cast<float4*>(&out[BH_ + base])      = x4;     // section 1: x
    *reinterpret_cast<float4*>(&out[2 * BH_ + base])  = o_naa;  // section 2: next_aa
    *reinterpret_cast<float4*>(&out[3 * BH_ + base])  = o_nbb;  // section 3: next_bb
    *reinterpret_cast<float4*>(&out[4 * BH_ + base])  = o_q2;   // section 4: qq2
}

extern "C" void kernel_launch(void* const* d_in, const int* in_sizes, int n_in,
                              void* d_out, int out_size)
{
    const float* x     = (const float*)d_in[0];
    const float* alpha = (const float*)d_in[1];
    const float* aa    = (const float*)d_in[2];
    const float* bb    = (const float*)d_in[3];
    const float* pp    = (const float*)d_in[4];
    const float* td    = (const float*)d_in[5];
    const float* tf    = (const float*)d_in[6];
    const float* tmk   = (const float*)d_in[7];
    const float* tmv   = (const float*)d_in[8];
    const float* tmr   = (const float*)d_in[9];
    const float* Wk    = (const float*)d_in[10];
    const float* Wv    = (const float*)d_in[11];
    const float* Wr    = (const float*)d_in[12];
    const float* Wo    = (const float*)d_in[13];
    float* out = (float*)d_out;

    dim3 g1(H_ / 128, B_ / 128, 3);
    gemm3_kernel<<<g1, 256>>>(x, alpha, tmk, tmv, tmr, Wk, Wv, Wr);

    wkv_kernel<<<BH_ / 1024, 256>>>(x, aa, bb, pp, td, tf, out);

    dim3 g2(H_ / 128, B_ / 128, 1);
    gemm_o_kernel<<<g2, 256>>>(Wo, out);
}

// round 5
// speedup vs baseline: 1.9397x; 1.9397x over previous
#include <cuda_runtime.h>
#include <cuda_bf16.h>
#include <cstdint>

#define B_  16384
#define H_  1024
#define BH_ (B_ * H_)
#define HH_ (H_ * H_)

// ---------------- device scratch ----------------
__device__ float g_k[BH_];
__device__ float g_v[BH_];
__device__ float g_r[BH_];
__device__ __nv_bfloat16 g_ah[3][BH_];   // mixed activations, hi split
__device__ __nv_bfloat16 g_al[3][BH_];   // mixed activations, lo split
__device__ __nv_bfloat16 g_rh[BH_];      // sigmoid(r)*wkv hi
__device__ __nv_bfloat16 g_rl[BH_];      // sigmoid(r)*wkv lo
__device__ __nv_bfloat16 g_wh[4][HH_];   // Wk,Wv,Wr,Wo hi
__device__ __nv_bfloat16 g_wl[4][HH_];   // Wk,Wv,Wr,Wo lo

// ---------------- PTX helpers (plain sm_103-legal: Ampere-era ISA) ----------------
__device__ __forceinline__ uint32_t smem_u32(const void* p) {
    uint32_t a;
    asm("{ .reg .u64 t; cvta.to.shared.u64 t, %1; cvt.u32.u64 %0, t; }" : "=r"(a) : "l"(p));
    return a;
}

#define CP16(s, g) asm volatile("cp.async.cg.shared.global [%0], [%1], 16;" :: "r"(s), "l"(g))
#define CP_COMMIT() asm volatile("cp.async.commit_group;" ::: "memory")
#define CP_WAIT(n)  asm volatile("cp.async.wait_group %0;" :: "n"(n) : "memory")

#define LDSM4(r, addr) \
    asm volatile("ldmatrix.sync.aligned.m8n8.x4.shared.b16 {%0,%1,%2,%3}, [%4];" \
        : "=r"((r)[0]), "=r"((r)[1]), "=r"((r)[2]), "=r"((r)[3]) : "r"(addr))

#define MMA16816(d, a, b) \
    asm volatile("mma.sync.aligned.m16n8k16.row.col.f32.bf16.bf16.f32 " \
        "{%0,%1,%2,%3}, {%4,%5,%6,%7}, {%8,%9}, {%0,%1,%2,%3};" \
        : "+f"((d)[0]), "+f"((d)[1]), "+f"((d)[2]), "+f"((d)[3]) \
        : "r"((a)[0]), "r"((a)[1]), "r"((a)[2]), "r"((a)[3]), \
          "r"((b)[0]), "r"((b)[1]))

// ---------------- bf16 hi/lo split ----------------
__device__ __forceinline__ void split4(const float4& v, uint2& hi, uint2& lo) {
    const float* f = reinterpret_cast<const float*>(&v);
    uint32_t hs[4], ls[4];
#pragma unroll
    for (int j = 0; j < 4; j++) {
        __nv_bfloat16 h = __float2bfloat16_rn(f[j]);
        __nv_bfloat16 l = __float2bfloat16_rn(f[j] - __bfloat162float(h));
        hs[j] = (uint32_t)__bfloat16_as_ushort(h);
        ls[j] = (uint32_t)__bfloat16_as_ushort(l);
    }
    hi.x = hs[0] | (hs[1] << 16); hi.y = hs[2] | (hs[3] << 16);
    lo.x = ls[0] | (ls[1] << 16); lo.y = ls[2] | (ls[3] << 16);
}

// ---------------- GEMM: C[B,1024] = (Ah+Al) @ (Wh+Wl)^T, 3-product bf16 split ----------------
// CTA tile 128x128, BK=16, 8 warps (warp tile 32x64), 4-stage cp.async pipeline.
static constexpr int STAGES    = 4;
static constexpr int STG_BYTES = 16384;           // Ah 4K | Al 4K | Bh 4K | Bl 4K
static constexpr int SMEM_BYTES = STAGES * STG_BYTES;  // 65536
static constexpr int KSTEPS    = H_ / 16;         // 64

__device__ __forceinline__ void load_stage(
    uint32_t sb, int stage,
    const __nv_bfloat16* __restrict__ ah, const __nv_bfloat16* __restrict__ al,
    const __nv_bfloat16* __restrict__ bh, const __nv_bfloat16* __restrict__ bl,
    int kt, int tid)
{
    const int row = tid >> 1;            // 0..127
    const int chunk = tid & 1;           // two 16B chunks per 32B row
    const uint32_t s = sb + stage * STG_BYTES + row * 32 + chunk * 16;
    const size_t g = (size_t)row * H_ + kt + chunk * 8;
    CP16(s,          ah + g);
    CP16(s + 4096,   al + g);
    CP16(s + 8192,   bh + g);
    CP16(s + 12288,  bl + g);
}

__device__ __forceinline__ void gemm_mma(
    const __nv_bfloat16* __restrict__ Ah, const __nv_bfloat16* __restrict__ Al,
    const __nv_bfloat16* __restrict__ Wh, const __nv_bfloat16* __restrict__ Wl,
    float* __restrict__ C)
{
    extern __shared__ char smem[];
    const uint32_t sb = smem_u32(smem);
    const int tid  = threadIdx.x;
    const int lane = tid & 31;
    const int w    = tid >> 5;
    const int wm   = (w & 3) * 32;       // warp M offset in CTA tile
    const int wn   = (w >> 2) * 64;      // warp N offset
    const int m0   = blockIdx.y * 128;
    const int n0   = blockIdx.x * 128;

    const __nv_bfloat16* pAh = Ah + (size_t)m0 * H_;
    const __nv_bfloat16* pAl = Al + (size_t)m0 * H_;
    const __nv_bfloat16* pBh = Wh + (size_t)n0 * H_;
    const __nv_bfloat16* pBl = Wl + (size_t)n0 * H_;

    float acc[2][8][4];
#pragma unroll
    for (int i = 0; i < 2; i++)
#pragma unroll
        for (int j = 0; j < 8; j++)
#pragma unroll
            for (int q = 0; q < 4; q++) acc[i][j][q] = 0.0f;

    // prefetch STAGES-1 stages
#pragma unroll
    for (int s = 0; s < STAGES - 1; ++s) {
        load_stage(sb, s, pAh, pAl, pBh, pBl, s * 16, tid);
        CP_COMMIT();
    }

    // ldmatrix base offsets for this lane
    const int lrow  = lane & 15;
    const int lchnk = (lane >> 4) * 16;

    for (int k = 0; k < KSTEPS; ++k) {
        CP_WAIT(STAGES - 2);
        __syncthreads();
        const uint32_t st = sb + (k & (STAGES - 1)) * STG_BYTES;

        // A fragments (2 m-tiles x {hi,lo})
        uint32_t ah[2][4], al[2][4];
#pragma unroll
        for (int mt = 0; mt < 2; ++mt) {
            const uint32_t a = st + (wm + mt * 16 + lrow) * 32 + lchnk;
            LDSM4(ah[mt], a);
            LDSM4(al[mt], a + 4096);
        }
        // B fragments (8 n-tiles x {hi,lo}); x4 loads 2 n-tiles
        uint32_t bh[8][2], bl[8][2];
#pragma unroll
        for (int q = 0; q < 4; ++q) {
            uint32_t r[4];
            const uint32_t a = st + 8192 + (wn + q * 16 + lrow) * 32 + lchnk;
            LDSM4(r, a);
            bh[2 * q][0] = r[0]; bh[2 * q + 1][0] = r[1];
            bh[2 * q][1] = r[2]; bh[2 * q + 1][1] = r[3];
            LDSM4(r, a + 4096);
            bl[2 * q][0] = r[0]; bl[2 * q + 1][0] = r[1];
            bl[2 * q][1] = r[2]; bl[2 * q + 1][1] = r[3];
        }

        // prefetch stage k+3
        if (k + STAGES - 1 < KSTEPS)
            load_stage(sb, (k + STAGES - 1) & (STAGES - 1), pAh, pAl, pBh, pBl,
                       (k + STAGES - 1) * 16, tid);
        CP_COMMIT();

        // 3-product split MMAs
#pragma unroll
        for (int mt = 0; mt < 2; ++mt)
#pragma unroll
            for (int nt = 0; nt < 8; ++nt) {
                MMA16816(acc[mt][nt], ah[mt], bh[nt]);
                MMA16816(acc[mt][nt], ah[mt], bl[nt]);
                MMA16816(acc[mt][nt], al[mt], bh[nt]);
            }
    }

    // epilogue: fp32 direct to global
    const int er = lane >> 2;
    const int ec = (lane & 3) * 2;
#pragma unroll
    for (int mt = 0; mt < 2; ++mt) {
        const int r0 = m0 + wm + mt * 16 + er;
#pragma unroll
        for (int nt = 0; nt < 8; ++nt) {
            const int c0 = n0 + wn + nt * 8 + ec;
            float2 lo2 = make_float2(acc[mt][nt][0], acc[mt][nt][1]);
            float2 hi2 = make_float2(acc[mt][nt][2], acc[mt][nt][3]);
            *reinterpret_cast<float2*>(&C[(size_t)r0 * H_ + c0])       = lo2;
            *reinterpret_cast<float2*>(&C[(size_t)(r0 + 8) * H_ + c0]) = hi2;
        }
    }
}

__global__ void __launch_bounds__(256, 1) gemm_kvr_kernel() {
    const int z = blockIdx.z;
    float* C = (z == 0) ? g_k : (z == 1) ? g_v : g_r;
    gemm_mma(g_ah[z], g_al[z], g_wh[z], g_wl[z], C);
}
__global__ void __launch_bounds__(256, 1) gemm_out_kernel(float* __restrict__ out) {
    gemm_mma(g_rh, g_rl, g_wh[3], g_wl[3], out);
}

// ---------------- pointwise kernels ----------------
__global__ void __launch_bounds__(256) mix_split_kernel(
    const float* __restrict__ x, const float* __restrict__ alpha,
    const float* __restrict__ tmk, const float* __restrict__ tmv,
    const float* __restrict__ tmr)
{
    const int base = (blockIdx.x * 256 + threadIdx.x) << 2;
    const int h = base & (H_ - 1);
    const float4 xv = *reinterpret_cast<const float4*>(x + base);
    const float4 av = *reinterpret_cast<const float4*>(alpha + base);
    const float4 tms[3] = {
        *reinterpret_cast<const float4*>(tmk + h),
        *reinterpret_cast<const float4*>(tmv + h),
        *reinterpret_cast<const float4*>(tmr + h)
    };
#pragma unroll
    for (int s = 0; s < 3; ++s) {
        float4 m;
        m.x = fmaf(xv.x - av.x, tms[s].x, av.x);
        m.y = fmaf(xv.y - av.y, tms[s].y, av.y);
        m.z = fmaf(xv.z - av.z, tms[s].z, av.z);
        m.w = fmaf(xv.w - av.w, tms[s].w, av.w);
        uint2 hi, lo;
        split4(m, hi, lo);
        *reinterpret_cast<uint2*>(&g_ah[s][base]) = hi;
        *reinterpret_cast<uint2*>(&g_al[s][base]) = lo;
    }
}

__global__ void __launch_bounds__(256) wsplit_kernel(
    const float* __restrict__ Wk, const float* __restrict__ Wv,
    const float* __restrict__ Wr, const float* __restrict__ Wo)
{
    const int w = blockIdx.y;
    const float* W = (w == 0) ? Wk : (w == 1) ? Wv : (w == 2) ? Wr : Wo;
    const int base = (blockIdx.x * 256 + threadIdx.x) << 2;
    const float4 v = *reinterpret_cast<const float4*>(W + base);
    uint2 hi, lo;
    split4(v, hi, lo);
    *reinterpret_cast<uint2*>(&g_wh[w][base]) = hi;
    *reinterpret_cast<uint2*>(&g_wl[w][base]) = lo;
}

__global__ void __launch_bounds__(256) wkv_kernel(
    const float* __restrict__ x,  const float* __restrict__ aa,
    const float* __restrict__ bb, const float* __restrict__ pp,
    const float* __restrict__ td, const float* __restrict__ tf,
    float* __restrict__ out)
{
    const int base = (blockIdx.x * 256 + threadIdx.x) << 2;
    const int h = base & (H_ - 1);

    const float4 k4  = *reinterpret_cast<const float4*>(&g_k[base]);
    const float4 v4  = *reinterpret_cast<const float4*>(&g_v[base]);
    const float4 r4  = *reinterpret_cast<const float4*>(&g_r[base]);
    const float4 a4  = *reinterpret_cast<const float4*>(&aa[base]);
    const float4 b4  = *reinterpret_cast<const float4*>(&bb[base]);
    const float4 p4  = *reinterpret_cast<const float4*>(&pp[base]);
    const float4 x4  = *reinterpret_cast<const float4*>(&x[base]);
    const float4 tf4 = *reinterpret_cast<const float4*>(&tf[h]);
    const float4 td4 = *reinterpret_cast<const float4*>(&td[h]);

    float4 o_rw, o_naa, o_nbb, o_q2;
    const float* kf = (const float*)&k4;  const float* vf = (const float*)&v4;
    const float* rf = (const float*)&r4;  const float* af = (const float*)&a4;
    const float* bf = (const float*)&b4;  const float* pf = (const float*)&p4;
    const float* tff = (const float*)&tf4; const float* tdf = (const float*)&td4;
    float* rw = (float*)&o_rw; float* naa = (float*)&o_naa;
    float* nbb = (float*)&o_nbb; float* oq2 = (float*)&o_q2;

#pragma unroll
    for (int j = 0; j < 4; j++) {
        const float k = kf[j], v = vf[j], a = af[j], b = bf[j], p = pf[j];
        const float r = 1.0f / (1.0f + expf(-rf[j]));

        const float ww  = tff[j] + k;
        const float qq  = fmaxf(p, ww);
        const float e1  = expf(p - qq);
        const float e2  = expf(ww - qq);
        const float wkv = (e1 * a + e2 * v) / (e1 * b + e2);
        rw[j] = r * wkv;

        const float ww2 = p + tdf[j];
        const float q2  = fmaxf(ww2, k);
        const float e1b = expf(ww2 - q2);
        const float e2b = expf(k - q2);
        naa[j] = e1b * a + e2b * v;
        nbb[j] = e1b * b + e2b;
        oq2[j] = q2;
    }

    uint2 hi, lo;
    split4(o_rw, hi, lo);
    *reinterpret_cast<uint2*>(&g_rh[base]) = hi;
    *reinterpret_cast<uint2*>(&g_rl[base]) = lo;

    *reinterpret_cast<float4*>(&out[(size_t)BH_ + base])     = x4;
    *reinterpret_cast<float4*>(&out[(size_t)2 * BH_ + base]) = o_naa;
    *reinterpret_cast<float4*>(&out[(size_t)3 * BH_ + base]) = o_nbb;
    *reinterpret_cast<float4*>(&out[(size_t)4 * BH_ + base]) = o_q2;
}

// ---------------- launch ----------------
extern "C" void kernel_launch(void* const* d_in, const int* in_sizes, int n_in,
                              void* d_out, int out_size)
{
    const float* x     = (const float*)d_in[0];
    const float* alpha = (const float*)d_in[1];
    const float* aa    = (const float*)d_in[2];
    const float* bb    = (const float*)d_in[3];
    const float* pp    = (const float*)d_in[4];
    const float* td    = (const float*)d_in[5];
    const float* tf    = (const float*)d_in[6];
    const float* tmk   = (const float*)d_in[7];
    const float* tmv   = (const float*)d_in[8];
    const float* tmr   = (const float*)d_in[9];
    const float* Wk    = (const float*)d_in[10];
    const float* Wv    = (const float*)d_in[11];
    const float* Wr    = (const float*)d_in[12];
    const float* Wo    = (const float*)d_in[13];
    float* out = (float*)d_out;

    cudaFuncSetAttribute(gemm_kvr_kernel, cudaFuncAttributeMaxDynamicSharedMemorySize, SMEM_BYTES);
    cudaFuncSetAttribute(gemm_out_kernel, cudaFuncAttributeMaxDynamicSharedMemorySize, SMEM_BYTES);

    wsplit_kernel<<<dim3(HH_ / 1024, 4), 256>>>(Wk, Wv, Wr, Wo);
    mix_split_kernel<<<BH_ / 1024, 256>>>(x, alpha, tmk, tmv, tmr);

    gemm_kvr_kernel<<<dim3(H_ / 128, B_ / 128, 3), 256, SMEM_BYTES>>>();

    wkv_kernel<<<BH_ / 1024, 256>>>(x, aa, bb, pp, td, tf, out);

    gemm_out_kernel<<<dim3(H_ / 128, B_ / 128, 1), 256, SMEM_BYTES>>>(out);
}

// round 6
// speedup vs baseline: 2.3537x; 1.2134x over previous
#include <cuda_runtime.h>
#include <cuda_bf16.h>
#include <cstdint>

#define B_  16384
#define H_  1024
#define BH_ (B_ * H_)
#define HH_ (H_ * H_)

// ---------------- device scratch ----------------
__device__ float g_k[BH_];
__device__ float g_v[BH_];
__device__ float g_r[BH_];
__device__ __nv_bfloat16 g_ah[3][BH_];   // mixed activations, hi split
__device__ __nv_bfloat16 g_al[3][BH_];   // mixed activations, lo split
__device__ __nv_bfloat16 g_rh[BH_];      // sigmoid(r)*wkv hi
__device__ __nv_bfloat16 g_rl[BH_];      // sigmoid(r)*wkv lo
__device__ __nv_bfloat16 g_wh[4][HH_];   // Wk,Wv,Wr,Wo hi
__device__ __nv_bfloat16 g_wl[4][HH_];   // Wk,Wv,Wr,Wo lo

// ---------------- PTX helpers (plain sm_103-legal) ----------------
__device__ __forceinline__ uint32_t smem_u32(const void* p) {
    uint32_t a;
    asm("{ .reg .u64 t; cvta.to.shared.u64 t, %1; cvt.u32.u64 %0, t; }" : "=r"(a) : "l"(p));
    return a;
}

#define CP16(s, g) asm volatile("cp.async.cg.shared.global [%0], [%1], 16;" :: "r"(s), "l"(g))
#define CP_COMMIT() asm volatile("cp.async.commit_group;" ::: "memory")
#define CP_WAIT(n)  asm volatile("cp.async.wait_group %0;" :: "n"(n) : "memory")

#define LDSM4(r, addr) \
    asm volatile("ldmatrix.sync.aligned.m8n8.x4.shared.b16 {%0,%1,%2,%3}, [%4];" \
        : "=r"((r)[0]), "=r"((r)[1]), "=r"((r)[2]), "=r"((r)[3]) : "r"(addr))

#define MMA16816(d, a, b) \
    asm volatile("mma.sync.aligned.m16n8k16.row.col.f32.bf16.bf16.f32 " \
        "{%0,%1,%2,%3}, {%4,%5,%6,%7}, {%8,%9}, {%0,%1,%2,%3};" \
        : "+f"((d)[0]), "+f"((d)[1]), "+f"((d)[2]), "+f"((d)[3]) \
        : "r"((a)[0]), "r"((a)[1]), "r"((a)[2]), "r"((a)[3]), \
          "r"((b)[0]), "r"((b)[1]))

// Conflict-free layout for 32B rows: XOR row bit2 into the 16B-chunk bit.
__device__ __forceinline__ uint32_t sw_off(int row, int chunk) {
    return (uint32_t)(row * 32 + (((chunk ^ (row >> 2)) & 1) << 4));
}

// ---------------- bf16 hi/lo split ----------------
__device__ __forceinline__ void split4(const float4& v, uint2& hi, uint2& lo) {
    const float* f = reinterpret_cast<const float*>(&v);
    uint32_t hs[4], ls[4];
#pragma unroll
    for (int j = 0; j < 4; j++) {
        __nv_bfloat16 h = __float2bfloat16_rn(f[j]);
        __nv_bfloat16 l = __float2bfloat16_rn(f[j] - __bfloat162float(h));
        hs[j] = (uint32_t)__bfloat16_as_ushort(h);
        ls[j] = (uint32_t)__bfloat16_as_ushort(l);
    }
    hi.x = hs[0] | (hs[1] << 16); hi.y = hs[2] | (hs[3] << 16);
    lo.x = ls[0] | (ls[1] << 16); lo.y = ls[2] | (ls[3] << 16);
}

// ---------------- GEMM: C = (Ah+Al) @ (Wh+Wl)^T, 3-product bf16 split ----------------
// CTA tile 64x128, BK=16, 4 warps (warp tile 32x64), 4-stage cp.async pipeline, 2 CTAs/SM.
static constexpr int STAGES     = 4;
static constexpr int STG_BYTES  = 12288;              // Ah 2K | Al 2K | Bh 4K | Bl 4K
static constexpr int OFF_AL     = 2048;
static constexpr int OFF_BH     = 4096;
static constexpr int OFF_BL     = 8192;
static constexpr int SMEM_BYTES = STAGES * STG_BYTES; // 49152
static constexpr int KSTEPS     = H_ / 16;            // 64

__device__ __forceinline__ void load_stage(
    uint32_t sb, int stage,
    const __nv_bfloat16* __restrict__ ah, const __nv_bfloat16* __restrict__ al,
    const __nv_bfloat16* __restrict__ bh, const __nv_bfloat16* __restrict__ bl,
    int kt, int tid)
{
    const int r = tid >> 1;          // 0..63
    const int c = tid & 1;           // 16B chunk
    const uint32_t base = sb + stage * STG_BYTES;
    const size_t g0 = (size_t)r * H_ + kt + c * 8;
    const size_t g1 = (size_t)(r + 64) * H_ + kt + c * 8;
    CP16(base +           sw_off(r, c),      ah + g0);
    CP16(base + OFF_AL  + sw_off(r, c),      al + g0);
    CP16(base + OFF_BH  + sw_off(r, c),      bh + g0);
    CP16(base + OFF_BH  + sw_off(r + 64, c), bh + g1);
    CP16(base + OFF_BL  + sw_off(r, c),      bl + g0);
    CP16(base + OFF_BL  + sw_off(r + 64, c), bl + g1);
}

__device__ __forceinline__ void gemm_mma(
    const __nv_bfloat16* __restrict__ Ah, const __nv_bfloat16* __restrict__ Al,
    const __nv_bfloat16* __restrict__ Wh, const __nv_bfloat16* __restrict__ Wl,
    float* __restrict__ C)
{
    extern __shared__ char smem[];
    const uint32_t sb = smem_u32(smem);
    const int tid  = threadIdx.x;
    const int lane = tid & 31;
    const int w    = tid >> 5;
    const int wm   = (w & 1) * 32;       // warp M offset (0/32)
    const int wn   = (w >> 1) * 64;      // warp N offset (0/64)
    const int m0   = blockIdx.y * 64;
    const int n0   = blockIdx.x * 128;

    const __nv_bfloat16* pAh = Ah + (size_t)m0 * H_;
    const __nv_bfloat16* pAl = Al + (size_t)m0 * H_;
    const __nv_bfloat16* pBh = Wh + (size_t)n0 * H_;
    const __nv_bfloat16* pBl = Wl + (size_t)n0 * H_;

    float acc[2][8][4];
#pragma unroll
    for (int i = 0; i < 2; i++)
#pragma unroll
        for (int j = 0; j < 8; j++)
#pragma unroll
            for (int q = 0; q < 4; q++) acc[i][j][q] = 0.0f;

#pragma unroll
    for (int s = 0; s < STAGES - 1; ++s) {
        load_stage(sb, s, pAh, pAl, pBh, pBl, s * 16, tid);
        CP_COMMIT();
    }

    const int lrow = lane & 15;
    const int lchk = lane >> 4;          // 0/1 -> 16B chunk selector

    for (int k = 0; k < KSTEPS; ++k) {
        CP_WAIT(STAGES - 2);
        __syncthreads();
        const uint32_t st = sb + (k & (STAGES - 1)) * STG_BYTES;

        // A fragments (2 m-tiles x {hi,lo})
        uint32_t ah[2][4], al[2][4];
#pragma unroll
        for (int mt = 0; mt < 2; ++mt) {
            const int row = wm + mt * 16 + lrow;
            LDSM4(ah[mt], st +          sw_off(row, lchk));
            LDSM4(al[mt], st + OFF_AL + sw_off(row, lchk));
        }
        // B fragments (8 n-tiles x {hi,lo}); each x4 covers 2 n-tiles
        uint32_t bh[8][2], bl[8][2];
#pragma unroll
        for (int q = 0; q < 4; ++q) {
            uint32_t r[4];
            const int row = wn + q * 16 + lrow;
            LDSM4(r, st + OFF_BH + sw_off(row, lchk));
            bh[2 * q][0] = r[0]; bh[2 * q + 1][0] = r[1];
            bh[2 * q][1] = r[2]; bh[2 * q + 1][1] = r[3];
            LDSM4(r, st + OFF_BL + sw_off(row, lchk));
            bl[2 * q][0] = r[0]; bl[2 * q + 1][0] = r[1];
            bl[2 * q][1] = r[2]; bl[2 * q + 1][1] = r[3];
        }

        if (k + STAGES - 1 < KSTEPS)
            load_stage(sb, (k + STAGES - 1) & (STAGES - 1), pAh, pAl, pBh, pBl,
                       (k + STAGES - 1) * 16, tid);
        CP_COMMIT();

        // Product-major: consecutive MMAs hit distinct accumulators (no RAW chains)
#pragma unroll
        for (int mt = 0; mt < 2; ++mt)
#pragma unroll
            for (int nt = 0; nt < 8; ++nt)
                MMA16816(acc[mt][nt], ah[mt], bh[nt]);
#pragma unroll
        for (int mt = 0; mt < 2; ++mt)
#pragma unroll
            for (int nt = 0; nt < 8; ++nt)
                MMA16816(acc[mt][nt], ah[mt], bl[nt]);
#pragma unroll
        for (int mt = 0; mt < 2; ++mt)
#pragma unroll
            for (int nt = 0; nt < 8; ++nt)
                MMA16816(acc[mt][nt], al[mt], bh[nt]);
    }

    // epilogue: fp32 direct to global
    const int er = lane >> 2;
    const int ec = (lane & 3) * 2;
#pragma unroll
    for (int mt = 0; mt < 2; ++mt) {
        const int r0 = m0 + wm + mt * 16 + er;
#pragma unroll
        for (int nt = 0; nt < 8; ++nt) {
            const int c0 = n0 + wn + nt * 8 + ec;
            float2 lo2 = make_float2(acc[mt][nt][0], acc[mt][nt][1]);
            float2 hi2 = make_float2(acc[mt][nt][2], acc[mt][nt][3]);
            *reinterpret_cast<float2*>(&C[(size_t)r0 * H_ + c0])       = lo2;
            *reinterpret_cast<float2*>(&C[(size_t)(r0 + 8) * H_ + c0]) = hi2;
        }
    }
}

__global__ void __launch_bounds__(128, 2) gemm_kvr_kernel() {
    const int z = blockIdx.z;
    float* C = (z == 0) ? g_k : (z == 1) ? g_v : g_r;
    gemm_mma(g_ah[z], g_al[z], g_wh[z], g_wl[z], C);
}
__global__ void __launch_bounds__(128, 2) gemm_out_kernel(float* __restrict__ out) {
    gemm_mma(g_rh, g_rl, g_wh[3], g_wl[3], out);
}

// ---------------- pointwise kernels ----------------
__global__ void __launch_bounds__(256) mix_split_kernel(
    const float* __restrict__ x, const float* __restrict__ alpha,
    const float* __restrict__ tmk, const float* __restrict__ tmv,
    const float* __restrict__ tmr)
{
    const int base = (blockIdx.x * 256 + threadIdx.x) << 2;
    const int h = base & (H_ - 1);
    const float4 xv = *reinterpret_cast<const float4*>(x + base);
    const float4 av = *reinterpret_cast<const float4*>(alpha + base);
    const float4 tms[3] = {
        *reinterpret_cast<const float4*>(tmk + h),
        *reinterpret_cast<const float4*>(tmv + h),
        *reinterpret_cast<const float4*>(tmr + h)
    };
#pragma unroll
    for (int s = 0; s < 3; ++s) {
        float4 m;
        m.x = fmaf(xv.x - av.x, tms[s].x, av.x);
        m.y = fmaf(xv.y - av.y, tms[s].y, av.y);
        m.z = fmaf(xv.z - av.z, tms[s].z, av.z);
        m.w = fmaf(xv.w - av.w, tms[s].w, av.w);
        uint2 hi, lo;
        split4(m, hi, lo);
        *reinterpret_cast<uint2*>(&g_ah[s][base]) = hi;
        *reinterpret_cast<uint2*>(&g_al[s][base]) = lo;
    }
}

__global__ void __launch_bounds__(256) wsplit_kernel(
    const float* __restrict__ Wk, const float* __restrict__ Wv,
    const float* __restrict__ Wr, const float* __restrict__ Wo)
{
    const int w = blockIdx.y;
    const float* W = (w == 0) ? Wk : (w == 1) ? Wv : (w == 2) ? Wr : Wo;
    const int base = (blockIdx.x * 256 + threadIdx.x) << 2;
    const float4 v = *reinterpret_cast<const float4*>(W + base);
    uint2 hi, lo;
    split4(v, hi, lo);
    *reinterpret_cast<uint2*>(&g_wh[w][base]) = hi;
    *reinterpret_cast<uint2*>(&g_wl[w][base]) = lo;
}

__global__ void __launch_bounds__(256) wkv_kernel(
    const float* __restrict__ x,  const float* __restrict__ aa,
    const float* __restrict__ bb, const float* __restrict__ pp,
    const float* __restrict__ td, const float* __restrict__ tf,
    float* __restrict__ out)
{
    const int base = (blockIdx.x * 256 + threadIdx.x) << 2;
    const int h = base & (H_ - 1);

    const float4 k4  = *reinterpret_cast<const float4*>(&g_k[base]);
    const float4 v4  = *reinterpret_cast<const float4*>(&g_v[base]);
    const float4 r4  = *reinterpret_cast<const float4*>(&g_r[base]);
    const float4 a4  = *reinterpret_cast<const float4*>(&aa[base]);
    const float4 b4  = *reinterpret_cast<const float4*>(&bb[base]);
    const float4 p4  = *reinterpret_cast<const float4*>(&pp[base]);
    const float4 x4  = *reinterpret_cast<const float4*>(&x[base]);
    const float4 tf4 = *reinterpret_cast<const float4*>(&tf[h]);
    const float4 td4 = *reinterpret_cast<const float4*>(&td[h]);

    float4 o_rw, o_naa, o_nbb, o_q2;
    const float* kf = (const float*)&k4;  const float* vf = (const float*)&v4;
    const float* rf = (const float*)&r4;  const float* af = (const float*)&a4;
    const float* bf = (const float*)&b4;  const float* pf = (const float*)&p4;
    const float* tff = (const float*)&tf4; const float* tdf = (const float*)&td4;
    float* rw = (float*)&o_rw; float* naa = (float*)&o_naa;
    float* nbb = (float*)&o_nbb; float* oq2 = (float*)&o_q2;

#pragma unroll
    for (int j = 0; j < 4; j++) {
        const float k = kf[j], v = vf[j], a = af[j], b = bf[j], p = pf[j];
        const float r = 1.0f / (1.0f + expf(-rf[j]));

        const float ww  = tff[j] + k;
        const float qq  = fmaxf(p, ww);
        const float e1  = expf(p - qq);
        const float e2  = expf(ww - qq);
        const float wkv = (e1 * a + e2 * v) / (e1 * b + e2);
        rw[j] = r * wkv;

        const float ww2 = p + tdf[j];
        const float q2  = fmaxf(ww2, k);
        const float e1b = expf(ww2 - q2);
        const float e2b = expf(k - q2);
        naa[j] = e1b * a + e2b * v;
        nbb[j] = e1b * b + e2b;
        oq2[j] = q2;
    }

    uint2 hi, lo;
    split4(o_rw, hi, lo);
    *reinterpret_cast<uint2*>(&g_rh[base]) = hi;
    *reinterpret_cast<uint2*>(&g_rl[base]) = lo;

    *reinterpret_cast<float4*>(&out[(size_t)BH_ + base])     = x4;
    *reinterpret_cast<float4*>(&out[(size_t)2 * BH_ + base]) = o_naa;
    *reinterpret_cast<float4*>(&out[(size_t)3 * BH_ + base]) = o_nbb;
    *reinterpret_cast<float4*>(&out[(size_t)4 * BH_ + base]) = o_q2;
}

// ---------------- launch ----------------
extern "C" void kernel_launch(void* const* d_in, const int* in_sizes, int n_in,
                              void* d_out, int out_size)
{
    const float* x     = (const float*)d_in[0];
    const float* alpha = (const float*)d_in[1];
    const float* aa    = (const float*)d_in[2];
    const float* bb    = (const float*)d_in[3];
    const float* pp    = (const float*)d_in[4];
    const float* td    = (const float*)d_in[5];
    const float* tf    = (const float*)d_in[6];
    const float* tmk   = (const float*)d_in[7];
    const float* tmv   = (const float*)d_in[8];
    const float* tmr   = (const float*)d_in[9];
    const float* Wk    = (const float*)d_in[10];
    const float* Wv    = (const float*)d_in[11];
    const float* Wr    = (const float*)d_in[12];
    const float* Wo    = (const float*)d_in[13];
    float* out = (float*)d_out;

    cudaFuncSetAttribute(gemm_kvr_kernel, cudaFuncAttributeMaxDynamicSharedMemorySize, SMEM_BYTES);
    cudaFuncSetAttribute(gemm_out_kernel, cudaFuncAttributeMaxDynamicSharedMemorySize, SMEM_BYTES);

    wsplit_kernel<<<dim3(HH_ / 1024, 4), 256>>>(Wk, Wv, Wr, Wo);
    mix_split_kernel<<<BH_ / 1024, 256>>>(x, alpha, tmk, tmv, tmr);

    gemm_kvr_kernel<<<dim3(H_ / 128, B_ / 64, 3), 128, SMEM_BYTES>>>();

    wkv_kernel<<<BH_ / 1024, 256>>>(x, aa, bb, pp, td, tf, out);

    gemm_out_kernel<<<dim3(H_ / 128, B_ / 64, 1), 128, SMEM_BYTES>>>(out);
}